// round 10
// baseline (speedup 1.0000x reference)
#include <cuda_runtime.h>
#include <cuda_fp16.h>
#include <math.h>

#define BB  16
#define NPT 1024
#define EPSW 1e-5f
#define L2E 1.4426950408889634f

#define SINK_JC   32      // j-chunks
#define SINK_ROWS 32      // rows per chunk
#define TROWS     4       // rows per pipeline tile (8KB)
#define NST       4       // pipeline stages

typedef unsigned long long ull;

// ---------------- scratch (static device globals; no allocations) ----------------
static __device__ __half g_Eh[BB][NPT][NPT];       // exp(affinity) fp16, 32MB, L2-resident
static __device__ float  g_part[SINK_JC][BB][NPT]; // col partial sums per j-chunk (2MB)
static __device__ float  g_ev[BB][NPT];            // folded exp(-v_k)
static __device__ float  g_refSoA[BB][6][NPT];
static __device__ float  g_gn[BB][NPT];
static __device__ float  g_featS[BB][6][NPT];
static __device__ float  g_fn[BB][NPT];
static __device__ float  g_eu[BB][NPT];            // exp(-u_j)
static __device__ float  g_w[BB][NPT];
static __device__ float  g_wrx[BB][NPT];
static __device__ float  g_wry[BB][NPT];
static __device__ float  g_wrz[BB][NPT];
static __device__ double g_T[BB][12];

__device__ __forceinline__ float fast_ex2(float x){ float y; asm("ex2.approx.ftz.f32 %0, %1;" : "=f"(y) : "f"(x)); return y; }
__device__ __forceinline__ int dval(const int* p, int d){ return p ? __ldg(p) : d; }
__device__ __forceinline__ unsigned smem_u32(const void* p){
    unsigned a; asm("{ .reg .u64 t; cvta.to.shared.u64 t, %1; cvt.u32.u64 %0, t; }" : "=r"(a) : "l"(p)); return a;
}
__device__ __forceinline__ void mbar_wait(unsigned mb, unsigned ph){
    asm volatile(
        "{\n\t.reg .pred P;\n\t"
        "WL_%=:\n\t"
        "mbarrier.try_wait.parity.acquire.cta.shared::cta.b64 P, [%0], %1, 0x989680;\n\t"
        "@P bra.uni WD_%=;\n\t"
        "bra.uni WL_%=;\n\t"
        "WD_%=:\n\t}"
        :: "r"(mb), "r"(ph) : "memory");
}
__device__ __forceinline__ void bulk_ld(unsigned dst, const void* src, unsigned bytes, unsigned mb){
    asm volatile("mbarrier.arrive.expect_tx.shared.b64 _, [%0], %1;" :: "r"(mb), "r"(bytes) : "memory");
    asm volatile("cp.async.bulk.shared::cta.global.mbarrier::complete_tx::bytes [%0], [%1], %2, [%3];"
                 :: "r"(dst), "l"(src), "r"(bytes), "r"(mb) : "memory");
}

// packed f32x2 helpers (Blackwell FFMA2)
__device__ __forceinline__ ull pack2(float lo, float hi){ ull r; asm("mov.b64 %0, {%1, %2};" : "=l"(r) : "f"(lo), "f"(hi)); return r; }
__device__ __forceinline__ void unpack2(ull v, float& lo, float& hi){ asm("mov.b64 {%0, %1}, %2;" : "=f"(lo), "=f"(hi) : "l"(v)); }
__device__ __forceinline__ ull fma2(ull a, ull b, ull c){ ull d; asm("fma.rn.f32x2 %0, %1, %2, %3;" : "=l"(d) : "l"(a), "l"(b), "l"(c)); return d; }
__device__ __forceinline__ ull add2(ull a, ull b){ ull d; asm("add.rn.f32x2 %0, %1, %2;" : "=l"(d) : "l"(a), "l"(b)); return d; }
__device__ __forceinline__ ull mul2(ull a, ull b){ ull d; asm("mul.rn.f32x2 %0, %1, %2;" : "=l"(d) : "l"(a), "l"(b)); return d; }

// ---------------- init ----------------
__global__ void k_init(const float* __restrict__ ref)
{
    int idx = blockIdx.x * 256 + threadIdx.x;
    if (idx < BB * NPT) {
        int b = idx >> 10, k = idx & 1023;
        const float* p = ref + (size_t)idx * 6;
        float n = 0.f;
#pragma unroll
        for (int c = 0; c < 6; c++) { float x = p[c]; g_refSoA[b][c][k] = x; n += x * x; }
        g_gn[b][k] = n;
    }
    if (idx < BB) {
        double* T = g_T[idx];
#pragma unroll
        for (int m = 0; m < 3; m++)
#pragma unroll
            for (int c = 0; c < 4; c++) T[m * 4 + c] = (m == c) ? 1.0 : 0.0;
    }
}

// ---------------- prep ----------------
__global__ void k_prep(const int* nreg, int r, const float* __restrict__ src)
{
    if (r >= dval(nreg, 3)) return;
    int idx = blockIdx.x * 256 + threadIdx.x;
    if (idx >= BB * NPT) return;
    int b = idx >> 10, j = idx & 1023;
    const double* T = g_T[b];
    const float* p = src + (size_t)idx * 6;
    float x = p[0], y = p[1], z = p[2], n3 = p[3], n4 = p[4], n5 = p[5];
    float q0 = (float)(T[0] * x + T[1] * y + T[2]  * z + T[3]);
    float q1 = (float)(T[4] * x + T[5] * y + T[6]  * z + T[7]);
    float q2 = (float)(T[8] * x + T[9] * y + T[10] * z + T[11]);
    g_featS[b][0][j] = q0; g_featS[b][1][j] = q1; g_featS[b][2][j] = q2;
    g_featS[b][3][j] = n3; g_featS[b][4][j] = n4; g_featS[b][5][j] = n5;
    g_fn[b][j] = q0*q0 + q1*q1 + q2*q2 + n3*n3 + n4*n4 + n5*n5;
}

// ---------------- mat: E = exp(a) (fp16) via f32x2, fused first row pass (ev==1) ----------------
__global__ void __launch_bounds__(256) k_mat(const int* nreg, int r,
                                             const float* __restrict__ beta_, const float* __restrict__ alpha_)
{
    if (r >= dval(nreg, 3)) return;
    int b = blockIdx.y;
    __shared__ float gs[6][NPT];
    __shared__ float pk[NPT];
    float bl = beta_[b] * L2E;
    for (int i = threadIdx.x; i < NPT; i += 256) {
#pragma unroll
        for (int c = 0; c < 6; c++) gs[c][i] = g_refSoA[b][c][i];
        pk[i] = bl * g_gn[b][i];
    }
    __syncthreads();
    int warp = threadIdx.x >> 5, lane = threadIdx.x & 31;
    int j0 = blockIdx.x * 32 + warp * 4;
    float al = alpha_[b];
    ull wj2[4][6], cj2[4];
#pragma unroll
    for (int t = 0; t < 4; t++) {
        int j = j0 + t;
#pragma unroll
        for (int c = 0; c < 6; c++) { float w = 2.f * bl * g_featS[b][c][j]; wj2[t][c] = pack2(w, w); }
        float cj = bl * (al - g_fn[b][j]);
        cj2[t] = pack2(cj, cj);
    }
    __half2* E0 = (__half2*)&g_Eh[b][j0][0];
    float acc[4] = {0.f, 0.f, 0.f, 0.f};
#pragma unroll 2
    for (int i = 0; i < 16; i++) {
        int kk = i * 32 + lane;
        ull g2[6];
#pragma unroll
        for (int c = 0; c < 6; c++) {
            float2 G = ((const float2*)&gs[c][0])[kk];
            g2[c] = pack2(G.x, G.y);
        }
        float2 P = ((const float2*)pk)[kk];
        ull pn = pack2(-P.x, -P.y);
#pragma unroll
        for (int t = 0; t < 4; t++) {
            ull a = add2(cj2[t], pn);
#pragma unroll
            for (int c = 0; c < 6; c++) a = fma2(wj2[t][c], g2[c], a);
            float ax, ay; unpack2(a, ax, ay);
            float e0 = fast_ex2(ax), e1 = fast_ex2(ay);
            E0[t * (NPT / 2) + kk] = __floats2half2_rn(e0, e1);
            acc[t] += e0 + e1;
        }
    }
#pragma unroll
    for (int t = 0; t < 4; t++)
#pragma unroll
        for (int o = 16; o; o >>= 1) acc[t] += __shfl_xor_sync(0xffffffffu, acc[t], o);
    if (lane == 0) {
#pragma unroll
        for (int t = 0; t < 4; t++) g_eu[b][j0 + t] = 1.f / (1.f + acc[t]);
    }
}

// ---------------- sink: ONE E sweep = row update (eu') + col partials, TMA-pipelined ----------------
// s==0: col partials only using g_eu (from mat). s>0: fold g_ev, eu' per row, partials with eu'.
__global__ void __launch_bounds__(256) k_sink(const int* nreg, const int* nsk, int r, int s)
{
    if (r >= dval(nreg, 3) || s >= dval(nsk, 5)) return;
    const int b = blockIdx.y, jc = blockIdx.x;
    const int j0 = jc * SINK_ROWS;
    const int t = threadIdx.x, w = t >> 5, lane = t & 31;
    const bool first = (s == 0);

    __shared__ __align__(16) __half tile[NST][TROWS][NPT];   // 32KB
    __shared__ float evs[NPT];
    __shared__ float eus_all[SINK_ROWS];
    __shared__ float redrow[TROWS][2];
    __shared__ __align__(8) ull mbar[NST];

    if (t < NST) {
        unsigned mb = smem_u32(&mbar[t]);
        asm volatile("mbarrier.init.shared.b64 [%0], %1;" :: "r"(mb), "r"(1) : "memory");
    }
    __syncthreads();
    asm volatile("fence.proxy.async.shared::cta;" ::: "memory");
    if (t == 0) {
#pragma unroll
        for (int p = 0; p < 3; p++)
            bulk_ld(smem_u32(&tile[p][0][0]), (const void*)&g_Eh[b][j0 + p * TROWS][0],
                    TROWS * NPT * 2, smem_u32(&mbar[p]));
    }
    if (first) {
        if (t < SINK_ROWS) eus_all[t] = g_eu[b][j0 + t];
    } else {
        ((float4*)evs)[t] = ((const float4*)&g_ev[b][0])[t];
    }
    __syncthreads();

    // per-warp fixed ev registers for row phase (k-set constant across tiles)
    float er[16];
    if (!first) {
        const int h = w & 1;
#pragma unroll
        for (int c = 0; c < 2; c++) {
            float4 f0 = *(const float4*)&evs[h * 512 + c * 256 + lane * 8];
            float4 f1 = *(const float4*)&evs[h * 512 + c * 256 + lane * 8 + 4];
            er[c*8+0]=f0.x; er[c*8+1]=f0.y; er[c*8+2]=f0.z; er[c*8+3]=f0.w;
            er[c*8+4]=f1.x; er[c*8+5]=f1.y; er[c*8+6]=f1.z; er[c*8+7]=f1.w;
        }
    }

    float acc0 = 0.f, acc1 = 0.f, acc2 = 0.f, acc3 = 0.f;
    const int NT = SINK_ROWS / TROWS;   // 8 tiles
    for (int tl = 0; tl < NT; tl++) {
        const int slot = tl & (NST - 1);
        const unsigned ph = (tl >> 2) & 1;
        mbar_wait(smem_u32(&mbar[slot]), ph);
        if (!first) {
            // row phase: warp pair per row (halves of k range)
            const int row = w >> 1, h = w & 1;
            const uint4* rp = (const uint4*)&tile[slot][row][h * 512];
            float sum = 0.f;
#pragma unroll
            for (int c = 0; c < 2; c++) {
                uint4 hv = rp[c * 32 + lane];
                float2 p0 = __half22float2(*(const __half2*)&hv.x);
                float2 p1 = __half22float2(*(const __half2*)&hv.y);
                float2 p2 = __half22float2(*(const __half2*)&hv.z);
                float2 p3 = __half22float2(*(const __half2*)&hv.w);
                const float* e = &er[c * 8];
                sum = fmaf(p0.x, e[0], sum); sum = fmaf(p0.y, e[1], sum);
                sum = fmaf(p1.x, e[2], sum); sum = fmaf(p1.y, e[3], sum);
                sum = fmaf(p2.x, e[4], sum); sum = fmaf(p2.y, e[5], sum);
                sum = fmaf(p3.x, e[6], sum); sum = fmaf(p3.y, e[7], sum);
            }
#pragma unroll
            for (int o = 16; o; o >>= 1) sum += __shfl_xor_sync(0xffffffffu, sum, o);
            if (lane == 0) redrow[row][h] = sum;
        }
        __syncthreads();
        float et[TROWS];
        if (first) {
#pragma unroll
            for (int q = 0; q < TROWS; q++) et[q] = eus_all[tl * TROWS + q];
        } else {
#pragma unroll
            for (int q = 0; q < TROWS; q++) et[q] = 1.f / (1.f + redrow[q][0] + redrow[q][1]);
            if (t < TROWS) eus_all[tl * TROWS + t] = et[t];
        }
        // col phase: thread t accumulates columns 4t..4t+3 over this tile's rows
#pragma unroll
        for (int q = 0; q < TROWS; q++) {
            uint2 hv = ((const uint2*)&tile[slot][q][0])[t];
            float2 q0 = __half22float2(*(const __half2*)&hv.x);
            float2 q1 = __half22float2(*(const __half2*)&hv.y);
            acc0 = fmaf(q0.x, et[q], acc0);
            acc1 = fmaf(q0.y, et[q], acc1);
            acc2 = fmaf(q1.x, et[q], acc2);
            acc3 = fmaf(q1.y, et[q], acc3);
        }
        __syncthreads();
        if (t == 0 && tl + 3 < NT) {
            int ns = (tl + 3) & (NST - 1);
            bulk_ld(smem_u32(&tile[ns][0][0]), (const void*)&g_Eh[b][j0 + (tl + 3) * TROWS][0],
                    TROWS * NPT * 2, smem_u32(&mbar[ns]));
        }
    }
    ((float4*)&g_part[jc][b][0])[t] = make_float4(acc0, acc1, acc2, acc3);
    if (!first && t < SINK_ROWS) g_eu[b][j0 + t] = eus_all[t];
}

// ---------------- fold: g_ev[b][k] = 1/(1 + sum_jc part[jc][b][k]) ----------------
__global__ void k_fold(const int* nreg, const int* nsk, int r, int s)
{
    if (r >= dval(nreg, 3) || s >= dval(nsk, 5)) return;
    int idx = blockIdx.x * 256 + threadIdx.x;     // 16384 threads
    int b = idx >> 10, k = idx & 1023;
    float sum = 0.f;
#pragma unroll
    for (int jc = 0; jc < SINK_JC; jc++) sum += g_part[jc][b][k];
    g_ev[b][k] = 1.f / (1.f + sum);
}

// ---------------- consume: exact fp32 recompute (f32x2); row sums, weighted ref, perm write ----------------
// grid (NPT/16, BB): 2 rows per warp
__global__ void __launch_bounds__(256) k_consume(const int* nreg, int r,
                                                 const float* __restrict__ beta_, const float* __restrict__ alpha_,
                                                 float* __restrict__ perm_out)
{
    int nr = dval(nreg, 3);
    if (r >= nr) return;
    bool last = (r == nr - 1);
    int b = blockIdx.y;
    __shared__ float gs[6][NPT];
    __shared__ float pk[NPT];
    __shared__ float evs[NPT];
    float bl = beta_[b] * L2E;
    for (int i = threadIdx.x; i < NPT; i += 256) {
#pragma unroll
        for (int c = 0; c < 6; c++) gs[c][i] = g_refSoA[b][c][i];
        pk[i] = bl * g_gn[b][i];
        evs[i] = g_ev[b][i];
    }
    __syncthreads();
    int warp = threadIdx.x >> 5, lane = threadIdx.x & 31;
    int j0 = blockIdx.x * 16 + warp * 2;
    float al = alpha_[b];
    ull wj2[2][6], cj2[2], eu2[2];
    float eu[2];
#pragma unroll
    for (int t = 0; t < 2; t++) {
        int j = j0 + t;
#pragma unroll
        for (int c = 0; c < 6; c++) { float wv = 2.f * bl * g_featS[b][c][j]; wj2[t][c] = pack2(wv, wv); }
        float cj = bl * (al - g_fn[b][j]);
        cj2[t] = pack2(cj, cj);
        eu[t] = g_eu[b][j];
        eu2[t] = pack2(eu[t], eu[t]);
    }
    ull S2[2] = {0ull, 0ull}, SX2[2] = {0ull, 0ull}, SY2[2] = {0ull, 0ull}, SZ2[2] = {0ull, 0ull};
    float2* pb0 = (float2*)(perm_out + ((size_t)(b * NPT + j0)) * NPT);
    float2* pb1 = (float2*)(perm_out + ((size_t)(b * NPT + j0 + 1)) * NPT);
#pragma unroll 2
    for (int i = 0; i < 16; i++) {
        int kk = i * 32 + lane;
        ull g2[6];
#pragma unroll
        for (int c = 0; c < 6; c++) {
            float2 G = ((const float2*)&gs[c][0])[kk];
            g2[c] = pack2(G.x, G.y);
        }
        float2 P = ((const float2*)pk)[kk];
        ull pn = pack2(-P.x, -P.y);
        float2 ev = ((const float2*)evs)[kk];
        ull evp = pack2(ev.x, ev.y);
#pragma unroll
        for (int t = 0; t < 2; t++) {
            ull a = add2(cj2[t], pn);
#pragma unroll
            for (int c = 0; c < 6; c++) a = fma2(wj2[t][c], g2[c], a);
            float ax, ay; unpack2(a, ax, ay);
            ull ee = mul2(pack2(fast_ex2(ax), fast_ex2(ay)), evp);
            S2[t]  = add2(S2[t], ee);
            SX2[t] = fma2(ee, g2[0], SX2[t]);
            SY2[t] = fma2(ee, g2[1], SY2[t]);
            SZ2[t] = fma2(ee, g2[2], SZ2[t]);
            if (last) {
                ull pw = mul2(ee, eu2[t]);
                float lo, hi; unpack2(pw, lo, hi);
                (t == 0 ? pb0 : pb1)[kk] = make_float2(lo, hi);
            }
        }
    }
    float S[2], SX[2], SY[2], SZ[2];
#pragma unroll
    for (int t = 0; t < 2; t++) {
        float lo, hi;
        unpack2(S2[t],  lo, hi); S[t]  = lo + hi;
        unpack2(SX2[t], lo, hi); SX[t] = lo + hi;
        unpack2(SY2[t], lo, hi); SY[t] = lo + hi;
        unpack2(SZ2[t], lo, hi); SZ[t] = lo + hi;
#pragma unroll
        for (int o = 16; o; o >>= 1) {
            S[t]  += __shfl_xor_sync(0xffffffffu, S[t],  o);
            SX[t] += __shfl_xor_sync(0xffffffffu, SX[t], o);
            SY[t] += __shfl_xor_sync(0xffffffffu, SY[t], o);
            SZ[t] += __shfl_xor_sync(0xffffffffu, SZ[t], o);
        }
    }
    if (lane == 0) {
#pragma unroll
        for (int t = 0; t < 2; t++) {
            int j = j0 + t;
            float W = S[t] * eu[t];
            g_w[b][j] = W;
            float inv = 1.f / (W + EPSW);
            g_wrx[b][j] = SX[t] * eu[t] * inv;
            g_wry[b][j] = SY[t] * eu[t] * inv;
            g_wrz[b][j] = SZ[t] * eu[t] * inv;
        }
    }
}

// ---------------- fit: weighted Kabsch (fp64 Jacobi SVD) + compose transform ----------------
__global__ void __launch_bounds__(256) k_fit(const int* nreg, int r, float* __restrict__ T_out)
{
    int nr = dval(nreg, 3);
    if (r >= nr) return;
    int b = blockIdx.x;
    int lane = threadIdx.x & 31, warp = threadIdx.x >> 5;
    __shared__ double sred[8][9];
    __shared__ double sc[8];

    double acc[7] = {0,0,0,0,0,0,0};
    for (int j = threadIdx.x; j < NPT; j += 256) {
        double w  = g_w[b][j];
        double ax = g_featS[b][0][j], ay = g_featS[b][1][j], az = g_featS[b][2][j];
        double bx = g_wrx[b][j], by = g_wry[b][j], bz = g_wrz[b][j];
        acc[0] += w;
        acc[1] += w*ax; acc[2] += w*ay; acc[3] += w*az;
        acc[4] += w*bx; acc[5] += w*by; acc[6] += w*bz;
    }
#pragma unroll
    for (int i = 0; i < 7; i++)
#pragma unroll
        for (int o = 16; o; o >>= 1) acc[i] += __shfl_xor_sync(0xffffffffu, acc[i], o);
    if (lane == 0)
#pragma unroll
        for (int i = 0; i < 7; i++) sred[warp][i] = acc[i];
    __syncthreads();
    if (threadIdx.x == 0) {
        double tot[7] = {0,0,0,0,0,0,0};
        for (int w = 0; w < 8; w++)
            for (int i = 0; i < 7; i++) tot[i] += sred[w][i];
        double den = tot[0] + 1e-5;
        sc[0] = den;
        for (int i = 0; i < 6; i++) sc[1 + i] = tot[1 + i] / den;
    }
    __syncthreads();
    double den = sc[0];
    double ca0 = sc[1], ca1 = sc[2], ca2 = sc[3];
    double cb0 = sc[4], cb1 = sc[5], cb2 = sc[6];

    double cv[9] = {0,0,0,0,0,0,0,0,0};
    for (int j = threadIdx.x; j < NPT; j += 256) {
        double wn = (double)g_w[b][j] / den;
        double ax = g_featS[b][0][j] - ca0, ay = g_featS[b][1][j] - ca1, az = g_featS[b][2][j] - ca2;
        double bx = g_wrx[b][j] - cb0, by = g_wry[b][j] - cb1, bz = g_wrz[b][j] - cb2;
        cv[0] += wn*ax*bx; cv[1] += wn*ax*by; cv[2] += wn*ax*bz;
        cv[3] += wn*ay*bx; cv[4] += wn*ay*by; cv[5] += wn*ay*bz;
        cv[6] += wn*az*bx; cv[7] += wn*az*by; cv[8] += wn*az*bz;
    }
#pragma unroll
    for (int i = 0; i < 9; i++)
#pragma unroll
        for (int o = 16; o; o >>= 1) cv[i] += __shfl_xor_sync(0xffffffffu, cv[i], o);
    if (lane == 0)
#pragma unroll
        for (int i = 0; i < 9; i++) sred[warp][i] = cv[i];
    __syncthreads();

    if (threadIdx.x == 0) {
        double C[3][3];
        {
            double tot[9] = {0,0,0,0,0,0,0,0,0};
            for (int w = 0; w < 8; w++)
                for (int i = 0; i < 9; i++) tot[i] += sred[w][i];
            for (int m = 0; m < 3; m++)
                for (int n = 0; n < 3; n++) C[m][n] = tot[m * 3 + n];
        }
        double A[3][3];
        for (int i = 0; i < 3; i++)
            for (int j = 0; j < 3; j++)
                A[i][j] = C[0][i]*C[0][j] + C[1][i]*C[1][j] + C[2][i]*C[2][j];
        double V[3][3] = {{1,0,0},{0,1,0},{0,0,1}};
        const int PP[3] = {0,0,1}, QQ[3] = {1,2,2};
        for (int sweep = 0; sweep < 30; sweep++) {
            double off = A[0][1]*A[0][1] + A[0][2]*A[0][2] + A[1][2]*A[1][2];
            if (off < 1e-26) break;
            for (int pi = 0; pi < 3; pi++) {
                int p = PP[pi], q = QQ[pi];
                double apq = A[p][q];
                if (fabs(apq) < 1e-300) continue;
                double theta = (A[q][q] - A[p][p]) / (2.0 * apq);
                double tt = ((theta >= 0.0) ? 1.0 : -1.0) / (fabs(theta) + sqrt(theta*theta + 1.0));
                double c = 1.0 / sqrt(tt*tt + 1.0), sn = tt * c;
                int m = 3 - p - q;
                double amp = A[m][p], amq = A[m][q];
                double app = A[p][p], aqq = A[q][q];
                A[p][p] = app - tt * apq;
                A[q][q] = aqq + tt * apq;
                A[p][q] = A[q][p] = 0.0;
                A[m][p] = A[p][m] = c*amp - sn*amq;
                A[m][q] = A[q][m] = sn*amp + c*amq;
                for (int mm = 0; mm < 3; mm++) {
                    double vp = V[mm][p], vq = V[mm][q];
                    V[mm][p] = c*vp - sn*vq;
                    V[mm][q] = sn*vp + c*vq;
                }
            }
        }
        double lam[3] = {A[0][0], A[1][1], A[2][2]};
        for (int i = 0; i < 2; i++)
            for (int j = i + 1; j < 3; j++)
                if (lam[j] > lam[i]) {
                    double tl = lam[i]; lam[i] = lam[j]; lam[j] = tl;
                    for (int m = 0; m < 3; m++) { double tv = V[m][i]; V[m][i] = V[m][j]; V[m][j] = tv; }
                }
        double v0[3] = {V[0][0], V[1][0], V[2][0]};
        double v1[3] = {V[0][1], V[1][1], V[2][1]};
        double v2[3] = {V[0][2], V[1][2], V[2][2]};
        double u0[3], u1[3], u2[3];
        for (int m = 0; m < 3; m++) {
            u0[m] = C[m][0]*v0[0] + C[m][1]*v0[1] + C[m][2]*v0[2];
            u1[m] = C[m][0]*v1[0] + C[m][1]*v1[1] + C[m][2]*v1[2];
            u2[m] = C[m][0]*v2[0] + C[m][1]*v2[1] + C[m][2]*v2[2];
        }
        double n0 = sqrt(u0[0]*u0[0] + u0[1]*u0[1] + u0[2]*u0[2]);
        if (n0 > 1e-150) { u0[0] /= n0; u0[1] /= n0; u0[2] /= n0; }
        else { u0[0] = 1; u0[1] = 0; u0[2] = 0; n0 = 0; }
        double d01 = u0[0]*u1[0] + u0[1]*u1[1] + u0[2]*u1[2];
        for (int m = 0; m < 3; m++) u1[m] -= d01 * u0[m];
        double n1 = sqrt(u1[0]*u1[0] + u1[1]*u1[1] + u1[2]*u1[2]);
        if (n1 > 1e-150) { u1[0] /= n1; u1[1] /= n1; u1[2] /= n1; }
        else {
            double e[3] = {0,0,0};
            e[(fabs(u0[0]) < 0.9) ? 0 : 1] = 1.0;
            double de = u0[0]*e[0] + u0[1]*e[1] + u0[2]*e[2];
            for (int m = 0; m < 3; m++) u1[m] = e[m] - de * u0[m];
            double nn = sqrt(u1[0]*u1[0] + u1[1]*u1[1] + u1[2]*u1[2]);
            for (int m = 0; m < 3; m++) u1[m] /= nn;
        }
        double d02 = u0[0]*u2[0] + u0[1]*u2[1] + u0[2]*u2[2];
        double d12 = u1[0]*u2[0] + u1[1]*u2[1] + u1[2]*u2[2];
        for (int m = 0; m < 3; m++) u2[m] -= d02 * u0[m] + d12 * u1[m];
        double n2 = sqrt(u2[0]*u2[0] + u2[1]*u2[1] + u2[2]*u2[2]);
        if (n2 > 1e-12 * (n0 + 1e-300)) { u2[0] /= n2; u2[1] /= n2; u2[2] /= n2; }
        else {
            u2[0] = u0[1]*u1[2] - u0[2]*u1[1];
            u2[1] = u0[2]*u1[0] - u0[0]*u1[2];
            u2[2] = u0[0]*u1[1] - u0[1]*u1[0];
        }
        double cx0 = u1[1]*u2[2] - u1[2]*u2[1];
        double cx1 = u1[2]*u2[0] - u1[0]*u2[2];
        double cx2 = u1[0]*u2[1] - u1[1]*u2[0];
        double detU = u0[0]*cx0 + u0[1]*cx1 + u0[2]*cx2;
        double cy0 = v1[1]*v2[2] - v1[2]*v2[1];
        double cy1 = v1[2]*v2[0] - v1[0]*v2[2];
        double cy2 = v1[0]*v2[1] - v1[1]*v2[0];
        double detV = v0[0]*cy0 + v0[1]*cy1 + v0[2]*cy2;
        double dd = (detU * detV >= 0.0) ? 1.0 : -1.0;
        double R[3][3];
        for (int m = 0; m < 3; m++)
            for (int n = 0; n < 3; n++)
                R[m][n] = v0[m]*u0[n] + v1[m]*u1[n] + dd * v2[m]*u2[n];
        double t3[3];
        t3[0] = cb0 - (R[0][0]*ca0 + R[0][1]*ca1 + R[0][2]*ca2);
        t3[1] = cb1 - (R[1][0]*ca0 + R[1][1]*ca1 + R[1][2]*ca2);
        t3[2] = cb2 - (R[2][0]*ca0 + R[2][1]*ca1 + R[2][2]*ca2);
        double* To = g_T[b];
        double Rn[9], tn[3];
        for (int m = 0; m < 3; m++) {
            for (int n = 0; n < 3; n++)
                Rn[m*3+n] = R[m][0]*To[0*4+n] + R[m][1]*To[1*4+n] + R[m][2]*To[2*4+n];
            tn[m] = R[m][0]*To[3] + R[m][1]*To[7] + R[m][2]*To[11] + t3[m];
        }
        for (int m = 0; m < 3; m++) {
            for (int n = 0; n < 3; n++) To[m*4+n] = Rn[m*3+n];
            To[m*4+3] = tn[m];
        }
        if (r == nr - 1 && T_out) {
            for (int m = 0; m < 3; m++)
                for (int n = 0; n < 4; n++)
                    T_out[b * 12 + m * 4 + n] = (float)To[m * 4 + n];
        }
    }
}

// ---------------- launch ----------------
extern "C" void kernel_launch(void* const* d_in, const int* in_sizes, int n_in,
                              void* d_out, int out_size)
{
    const float* src   = (const float*)d_in[0];
    const float* ref   = (const float*)d_in[1];
    const float* beta  = (const float*)d_in[2];
    const float* alpha = (const float*)d_in[3];
    const int*   nreg  = (n_in > 4) ? (const int*)d_in[4] : nullptr;
    const int*   nsk   = (n_in > 5) ? (const int*)d_in[5] : nullptr;

    float* out = (float*)d_out;
    const long permN = (long)BB * NPT * NPT;
    long off = (long)out_size - permN;
    if (off < 0) off = 0;
    float* perm_out = out + off;
    float* T_out = (off >= BB * 12) ? out : nullptr;

    k_init<<<64, 256>>>(ref);
    const int RMAX = 3, SMAX = 5;
    dim3 gridMat(NPT / 32, BB);      // 512 blocks
    dim3 gridSink(SINK_JC, BB);      // 512 blocks
    dim3 gridCons(NPT / 16, BB);     // 1024 blocks
    for (int r = 0; r < RMAX; r++) {
        k_prep<<<64, 256>>>(nreg, r, src);
        k_mat<<<gridMat, 256>>>(nreg, r, beta, alpha);     // writes fp16 E + eu1 (row pass, ev==1)
        for (int s = 0; s < SMAX; s++) {
            k_sink<<<gridSink, 256>>>(nreg, nsk, r, s);    // one E sweep: eu_{s+1} (s>0) + partials
            k_fold<<<64, 256>>>(nreg, nsk, r, s);          // partials -> g_ev
        }
        k_consume<<<gridCons, 256>>>(nreg, r, beta, alpha, perm_out);
        k_fit<<<BB, 256>>>(nreg, r, T_out);
    }
}